// round 2
// baseline (speedup 1.0000x reference)
#include <cuda_runtime.h>
#include <cuda_fp16.h>
#include <cstdint>

#define DEV_INLINE __device__ __forceinline__

// ---------------- problem constants (fixed shapes) ----------------
constexpr int Bc = 4, Tc = 2048, Dc = 4096, OUTc = 4096, RANKc = 128, SELECTc = 128, GROUPc = 16;
constexpr int MTOK = Bc * Tc;         // 8192 token rows
constexpr int SPARSE_T = 204;         // int(2048 * (1 - 0.9))
constexpr float SCALE_CAP = 448.0f * 6.0f;

// ---------------- scratch (device globals; no allocation APIs) ----------------
// split-fp16 representation: value ~= h + l, each fp16.
__device__ __half  g_Xh [(size_t)MTOK * Dc];
__device__ __half  g_Xl [(size_t)MTOK * Dc];
__device__ __half  g_LRh[(size_t)MTOK * Dc];
__device__ __half  g_LRl[(size_t)MTOK * Dc];
__device__ __half  g_Whh[(size_t)OUTc * Dc];
__device__ __half  g_Wll[(size_t)OUTc * Dc];
__device__ __half  g_vsh[(size_t)RANKc * Dc];   // vs^T [r][d]
__device__ __half  g_vsl[(size_t)RANKc * Dc];
__device__ __half  g_uth[(size_t)OUTc * RANKc]; // u_t^T [o][r]
__device__ __half  g_utl[(size_t)OUTc * RANKc];
__device__ __half  g_tmph[(size_t)MTOK * RANKc];
__device__ __half  g_tmpl[(size_t)MTOK * RANKc];
__device__ unsigned g_maxbits[2];               // absmax bits: [0]=prefill, [1]=decode(masked)
__device__ float    g_s[2];                     // finalized scales

DEV_INLINE void split2(float v, __half& h, __half& l) {
    __half hh = __float2half(v);
    h = hh;
    l = __float2half(v - __half2float(hh));
}

// ---------------- small kernels ----------------
__global__ void init_kernel() {
    if (threadIdx.x < 2) g_maxbits[threadIdx.x] = 0u;
}

__global__ void reduce_max_kernel(const float* __restrict__ x,
                                  const float* __restrict__ scale_vec,
                                  const float* __restrict__ threshold) {
    const float thr = threshold[0];
    float mpre = 0.f, mdec = 0.f;
    const size_t n = (size_t)MTOK * Dc;
    for (size_t i = (size_t)blockIdx.x * blockDim.x + threadIdx.x; i < n;
         i += (size_t)gridDim.x * blockDim.x) {
        int d = (int)(i & (Dc - 1));
        int t = (int)((i >> 12) & (Tc - 1));   // Dc = 2^12, Tc = 2^11
        float v = x[i];
        float av = fabsf(v);
        if (t < SPARSE_T) {
            mpre = fmaxf(mpre, av);
        } else {
            if (fabsf(v * scale_vec[d]) > thr) mdec = fmaxf(mdec, av);
        }
    }
#pragma unroll
    for (int o = 16; o; o >>= 1) {
        mpre = fmaxf(mpre, __shfl_xor_sync(0xffffffffu, mpre, o));
        mdec = fmaxf(mdec, __shfl_xor_sync(0xffffffffu, mdec, o));
    }
    __shared__ float spre[8], sdec[8];
    int w = threadIdx.x >> 5;
    if ((threadIdx.x & 31) == 0) { spre[w] = mpre; sdec[w] = mdec; }
    __syncthreads();
    if (threadIdx.x == 0) {
        float a = spre[0], b = sdec[0];
        for (int i = 1; i < (int)(blockDim.x >> 5); i++) {
            a = fmaxf(a, spre[i]); b = fmaxf(b, sdec[i]);
        }
        atomicMax(&g_maxbits[0], __float_as_uint(a));
        atomicMax(&g_maxbits[1], __float_as_uint(b));
    }
}

__global__ void finalize_s_kernel() {
    if (threadIdx.x < 2) {
        float m = __uint_as_float(g_maxbits[threadIdx.x]);
        g_s[threadIdx.x] = fmaxf(m / SCALE_CAP, 1e-12f);
    }
}

// fp4 magnitude rounding, exact replica of searchsorted(bounds, |a|, side='left')
DEV_INLINE float fp4_mag(float a) {
    return a > 2.5f ? (a > 3.5f ? (a > 5.0f ? 6.0f : 4.0f) : 3.0f)
                    : (a > 1.25f ? (a > 1.75f ? 2.0f : 1.5f)
                                 : (a > 0.75f ? 1.0f : (a > 0.25f ? 0.5f : 0.0f)));
}

// One block per token. Quantizes in REORDERED space, scatters back to ORIGINAL
// column order (so GEMM uses W untouched). Output stored as split-fp16.
__global__ void __launch_bounds__(256) quantize_kernel(const float* __restrict__ x,
                                                       const float* __restrict__ scale_vec,
                                                       const float* __restrict__ threshold,
                                                       const int* __restrict__ rix) {
    __shared__ float  sx[Dc];
    __shared__ int    sri[Dc];
    __shared__ float  sq[Dc];

    const int tok = blockIdx.x;
    const int t = tok & (Tc - 1);
    const bool decode = (t >= SPARSE_T);
    const float thr = threshold[0];
    const float s = decode ? g_s[1] : g_s[0];
    const float* xrow = x + (size_t)tok * Dc;
    const int tid = threadIdx.x;

    __half* lrh = g_LRh + (size_t)tok * Dc;
    __half* lrl = g_LRl + (size_t)tok * Dc;

    for (int i = tid; i < Dc; i += 256) {
        float v = xrow[i];
        sri[i] = rix[i];
        float masked, lr;
        if (decode) {
            bool m = fabsf(v * scale_vec[i]) > thr;
            masked = m ? v : 0.0f;
            lr     = m ? 0.0f : v;
        } else {
            masked = v; lr = 0.0f;
        }
        sx[i] = masked;
        __half h, l; split2(lr, h, l);
        lrh[i] = h; lrl[i] = l;
    }
    __syncthreads();

    if (tid < 8) {
        // "hi" region: first SELECT=128 reordered columns, (x/s)*s unquantized
#pragma unroll
        for (int k = 0; k < 16; k++) {
            int j = tid * 16 + k;
            int ri = sri[j];
            float xr = sx[ri] / s;
            sq[ri] = xr * s;
        }
    } else {
        // "lo" region: 248 groups of 16
        int g = tid - 8;
        int j0 = SELECTc + g * GROUPc;
        float vals[GROUPc];
        int ris[GROUPc];
        float gmax = 0.f;
#pragma unroll
        for (int k = 0; k < GROUPc; k++) {
            int ri = sri[j0 + k];
            ris[k] = ri;
            float v = sx[ri] / s;
            vals[k] = v;
            gmax = fmaxf(gmax, fabsf(v));
        }
        float gs = (gmax > 0.f) ? (gmax / 6.0f) : 1.0f;
#pragma unroll
        for (int k = 0; k < GROUPc; k++) {
            float r = vals[k] / gs;
            float q = fp4_mag(fabsf(r));
            q = (r < 0.f) ? -q : q;
            sq[ris[k]] = (q * gs) * s;
        }
    }
    __syncthreads();

    __half* xh = g_Xh + (size_t)tok * Dc;
    __half* xl = g_Xl + (size_t)tok * Dc;
    for (int i = tid; i < Dc; i += 256) {
        __half h, l; split2(sq[i], h, l);
        xh[i] = h; xl[i] = l;
    }
}

__global__ void convert_w_kernel(const float* __restrict__ W) {
    const size_t n = (size_t)OUTc * Dc;
    for (size_t i = (size_t)blockIdx.x * blockDim.x + threadIdx.x; i < n;
         i += (size_t)gridDim.x * blockDim.x) {
        __half h, l; split2(W[i], h, l);
        g_Whh[i] = h; g_Wll[i] = l;
    }
}

__global__ void convert_small_kernel(const float* __restrict__ vs, const float* __restrict__ u_t) {
    const int n = Dc * RANKc; // == RANKc * OUTc
    int stride = gridDim.x * blockDim.x;
    for (int i = blockIdx.x * blockDim.x + threadIdx.x; i < n; i += stride) {
        int d = i / RANKc, r = i - d * RANKc;        // vs is [D][RANK]
        __half h, l; split2(vs[i], h, l);
        g_vsh[(size_t)r * Dc + d] = h;
        g_vsl[(size_t)r * Dc + d] = l;
    }
    for (int i = blockIdx.x * blockDim.x + threadIdx.x; i < n; i += stride) {
        int r = i / OUTc, o = i - r * OUTc;          // u_t is [RANK][OUT]
        __half h, l; split2(u_t[i], h, l);
        g_uth[(size_t)o * RANKc + r] = h;
        g_utl[(size_t)o * RANKc + r] = l;
    }
}

// ---------------- split-fp16 GEMM (exact-product: Ah*Bh + Al*Bh + Ah*Bl) ----------------
DEV_INLINE unsigned smem_u32(const void* p) { return (unsigned)__cvta_generic_to_shared(p); }

DEV_INLINE void cp_async16(unsigned dst, const void* src) {
    asm volatile("cp.async.cg.shared.global [%0], [%1], 16;\n" :: "r"(dst), "l"(src));
}
DEV_INLINE void cp_commit() { asm volatile("cp.async.commit_group;\n"); }
template <int N> DEV_INLINE void cp_wait() { asm volatile("cp.async.wait_group %0;\n" :: "n"(N)); }

DEV_INLINE void ldmatrix_x4(unsigned& r0, unsigned& r1, unsigned& r2, unsigned& r3, unsigned addr) {
    asm volatile("ldmatrix.sync.aligned.m8n8.x4.shared.b16 {%0,%1,%2,%3}, [%4];\n"
                 : "=r"(r0), "=r"(r1), "=r"(r2), "=r"(r3) : "r"(addr));
}
DEV_INLINE void mma16816(float& d0, float& d1, float& d2, float& d3,
                         unsigned a0, unsigned a1, unsigned a2, unsigned a3,
                         unsigned b0, unsigned b1) {
    asm volatile("mma.sync.aligned.m16n8k16.row.col.f32.f16.f16.f32 "
                 "{%0,%1,%2,%3}, {%4,%5,%6,%7}, {%8,%9}, {%0,%1,%2,%3};\n"
                 : "+f"(d0), "+f"(d1), "+f"(d2), "+f"(d3)
                 : "r"(a0), "r"(a1), "r"(a2), "r"(a3), "r"(b0), "r"(b1));
}

// C[M,N] = (Ah+Al)[M,K] * ((Bh+Bl)[N,K])^T   (K-contiguous fp16 splits)
// EPI 0: write split-fp16 C  (Cv = hi array, Cv2 = lo array)
// EPI 1: write float C = acc
// EPI 2: float C = C + acc + bias[col]
template <int EPI>
__global__ void __launch_bounds__(256)
gemm_nt_split_kernel(const __half* __restrict__ Ah, const __half* __restrict__ Al,
                     const __half* __restrict__ Bh, const __half* __restrict__ Bl,
                     void* __restrict__ Cv, void* __restrict__ Cv2,
                     const float* __restrict__ bias,
                     int M, int N, int K) {
    constexpr int BM = 128, BN = 128, BK = 32;
    extern __shared__ uint4 smem_dyn[];
    uint4* sAh = smem_dyn;                 // [2][BM*4]
    uint4* sAl = sAh + 2 * BM * 4;
    uint4* sBh = sAl + 2 * BM * 4;
    uint4* sBl = sBh + 2 * BN * 4;

    const int tid = threadIdx.x;
    const int rowA0 = blockIdx.y * BM;
    const int rowB0 = blockIdx.x * BN;
    const int KT = K / BK;

    auto load_tile = [&](int stage, int kt) {
        const int k0 = kt * BK;
        const int so = stage * BM * 4;
#pragma unroll
        for (int i = tid; i < BM * 4; i += 256) {
            int m = i >> 2, kc = i & 3;
            int dst = so + m * 4 + (kc ^ ((m >> 1) & 3));
            size_t src = (size_t)(rowA0 + m) * K + k0 + kc * 8;
            cp_async16(smem_u32(&sAh[dst]), Ah + src);
            cp_async16(smem_u32(&sAl[dst]), Al + src);
        }
#pragma unroll
        for (int i = tid; i < BN * 4; i += 256) {
            int n = i >> 2, kc = i & 3;
            int dst = so + n * 4 + (kc ^ ((n >> 1) & 3));
            size_t src = (size_t)(rowB0 + n) * K + k0 + kc * 8;
            cp_async16(smem_u32(&sBh[dst]), Bh + src);
            cp_async16(smem_u32(&sBl[dst]), Bl + src);
        }
        cp_commit();
    };

    const int warp = tid >> 5, lane = tid & 31;
    const int wm = warp & 1;    // 2 warp-rows of 64
    const int wn = warp >> 1;   // 4 warp-cols of 32

    float acc[4][4][4];
#pragma unroll
    for (int i = 0; i < 4; i++)
#pragma unroll
        for (int j = 0; j < 4; j++)
#pragma unroll
            for (int k = 0; k < 4; k++) acc[i][j][k] = 0.f;

    load_tile(0, 0);
    load_tile(1, 1);
    int cur = 0;

    for (int kt = 0; kt < KT; kt++) {
        cp_wait<1>();
        __syncthreads();
        const int so = cur * BM * 4;
#pragma unroll
        for (int ks = 0; ks < 2; ks++) {
            unsigned ah[4][4], al[4][4];
#pragma unroll
            for (int mi = 0; mi < 4; mi++) {
                int m = wm * 64 + mi * 16 + (lane & 15);
                int kc = ks * 2 + (lane >> 4);
                int idx = so + m * 4 + (kc ^ ((m >> 1) & 3));
                ldmatrix_x4(ah[mi][0], ah[mi][1], ah[mi][2], ah[mi][3], smem_u32(&sAh[idx]));
                ldmatrix_x4(al[mi][0], al[mi][1], al[mi][2], al[mi][3], smem_u32(&sAl[idx]));
            }
            unsigned bh[4][2], bl[4][2];
#pragma unroll
            for (int nb = 0; nb < 2; nb++) {
                int n = wn * 32 + nb * 16 + (lane & 7) + ((lane >> 4) << 3);
                int kc = ks * 2 + ((lane >> 3) & 1);
                int idx = so + n * 4 + (kc ^ ((n >> 1) & 3));
                unsigned r0, r1, r2, r3;
                ldmatrix_x4(r0, r1, r2, r3, smem_u32(&sBh[idx]));
                bh[nb * 2][0] = r0;     bh[nb * 2][1] = r1;
                bh[nb * 2 + 1][0] = r2; bh[nb * 2 + 1][1] = r3;
                ldmatrix_x4(r0, r1, r2, r3, smem_u32(&sBl[idx]));
                bl[nb * 2][0] = r0;     bl[nb * 2][1] = r1;
                bl[nb * 2 + 1][0] = r2; bl[nb * 2 + 1][1] = r3;
            }
#pragma unroll
            for (int mi = 0; mi < 4; mi++)
#pragma unroll
                for (int ni = 0; ni < 4; ni++) {
                    float* d = acc[mi][ni];
                    mma16816(d[0], d[1], d[2], d[3],
                             ah[mi][0], ah[mi][1], ah[mi][2], ah[mi][3], bh[ni][0], bh[ni][1]);
                    mma16816(d[0], d[1], d[2], d[3],
                             al[mi][0], al[mi][1], al[mi][2], al[mi][3], bh[ni][0], bh[ni][1]);
                    mma16816(d[0], d[1], d[2], d[3],
                             ah[mi][0], ah[mi][1], ah[mi][2], ah[mi][3], bl[ni][0], bl[ni][1]);
                }
        }
        __syncthreads();
        if (kt + 2 < KT) load_tile(cur, kt + 2);
        cur ^= 1;
    }

    // epilogue
    const int crow0 = rowA0 + wm * 64;
    const int ccol0 = rowB0 + wn * 32;
#pragma unroll
    for (int mi = 0; mi < 4; mi++) {
#pragma unroll
        for (int ni = 0; ni < 4; ni++) {
            int r = crow0 + mi * 16 + (lane >> 2);
            int c = ccol0 + ni * 8 + (lane & 3) * 2;
            size_t i0 = (size_t)r * N + c;
            size_t i1 = (size_t)(r + 8) * N + c;
            float* d = acc[mi][ni];
            if (EPI == 0) {
                __half* Ch = (__half*)Cv;
                __half* Cl = (__half*)Cv2;
                __half h0, l0, h1, l1;
                split2(d[0], h0, l0); split2(d[1], h1, l1);
                *reinterpret_cast<__half2*>(Ch + i0) = __halves2half2(h0, h1);
                *reinterpret_cast<__half2*>(Cl + i0) = __halves2half2(l0, l1);
                split2(d[2], h0, l0); split2(d[3], h1, l1);
                *reinterpret_cast<__half2*>(Ch + i1) = __halves2half2(h0, h1);
                *reinterpret_cast<__half2*>(Cl + i1) = __halves2half2(l0, l1);
            } else if (EPI == 1) {
                float* C = (float*)Cv;
                *reinterpret_cast<float2*>(C + i0) = make_float2(d[0], d[1]);
                *reinterpret_cast<float2*>(C + i1) = make_float2(d[2], d[3]);
            } else {
                float* C = (float*)Cv;
                float b0 = bias[c], b1 = bias[c + 1];
                float2 o0 = *reinterpret_cast<float2*>(C + i0);
                float2 o1 = *reinterpret_cast<float2*>(C + i1);
                *reinterpret_cast<float2*>(C + i0) = make_float2(d[0] + b0 + o0.x, d[1] + b1 + o0.y);
                *reinterpret_cast<float2*>(C + i1) = make_float2(d[2] + b0 + o1.x, d[3] + b1 + o1.y);
            }
        }
    }
}

// ---------------- launch ----------------
extern "C" void kernel_launch(void* const* d_in, const int* in_sizes, int n_in,
                              void* d_out, int out_size) {
    const float* x         = (const float*)d_in[0];
    const float* W         = (const float*)d_in[1];
    const float* bias      = (const float*)d_in[2];
    const float* vs        = (const float*)d_in[3];
    const float* u_t       = (const float*)d_in[4];
    const float* scale_vec = (const float*)d_in[5];
    const float* threshold = (const float*)d_in[6];
    const int*   rix       = (const int*)d_in[7];

    void *pXh, *pXl, *pLRh, *pLRl, *pWhh, *pWll, *pvsh, *pvsl, *puth, *putl, *ptmph, *ptmpl;
    cudaGetSymbolAddress(&pXh,  g_Xh);
    cudaGetSymbolAddress(&pXl,  g_Xl);
    cudaGetSymbolAddress(&pLRh, g_LRh);
    cudaGetSymbolAddress(&pLRl, g_LRl);
    cudaGetSymbolAddress(&pWhh, g_Whh);
    cudaGetSymbolAddress(&pWll, g_Wll);
    cudaGetSymbolAddress(&pvsh, g_vsh);
    cudaGetSymbolAddress(&pvsl, g_vsl);
    cudaGetSymbolAddress(&puth, g_uth);
    cudaGetSymbolAddress(&putl, g_utl);
    cudaGetSymbolAddress(&ptmph, g_tmph);
    cudaGetSymbolAddress(&ptmpl, g_tmpl);

    constexpr int SMEM_GEMM = 2 * (128 * 4 + 128 * 4 + 128 * 4 + 128 * 4) * 16; // 64 KB
    cudaFuncSetAttribute(gemm_nt_split_kernel<0>, cudaFuncAttributeMaxDynamicSharedMemorySize, SMEM_GEMM);
    cudaFuncSetAttribute(gemm_nt_split_kernel<1>, cudaFuncAttributeMaxDynamicSharedMemorySize, SMEM_GEMM);
    cudaFuncSetAttribute(gemm_nt_split_kernel<2>, cudaFuncAttributeMaxDynamicSharedMemorySize, SMEM_GEMM);

    init_kernel<<<1, 32>>>();
    reduce_max_kernel<<<1184, 256>>>(x, scale_vec, threshold);
    finalize_s_kernel<<<1, 32>>>();
    quantize_kernel<<<MTOK, 256>>>(x, scale_vec, threshold, rix);
    convert_w_kernel<<<2048, 256>>>(W);
    convert_small_kernel<<<512, 256>>>(vs, u_t);

    // low-rank: tmp = LR @ vs   (M=8192, N=128, K=4096), split output
    {
        dim3 grid(RANKc / 128, MTOK / 128);
        gemm_nt_split_kernel<0><<<grid, 256, SMEM_GEMM>>>(
            (const __half*)pLRh, (const __half*)pLRl,
            (const __half*)pvsh, (const __half*)pvsl,
            ptmph, ptmpl, nullptr, MTOK, RANKc, Dc);
    }
    // out = tmp @ u_t   (M=8192, N=4096, K=128) — writes every output element
    {
        dim3 grid(OUTc / 128, MTOK / 128);
        gemm_nt_split_kernel<1><<<grid, 256, SMEM_GEMM>>>(
            (const __half*)ptmph, (const __half*)ptmpl,
            (const __half*)puth, (const __half*)putl,
            d_out, nullptr, nullptr, MTOK, OUTc, RANKc);
    }
    // out += Xq @ W^T + bias   (M=8192, N=4096, K=4096)
    {
        dim3 grid(OUTc / 128, MTOK / 128);
        gemm_nt_split_kernel<2><<<grid, 256, SMEM_GEMM>>>(
            (const __half*)pXh, (const __half*)pXl,
            (const __half*)pWhh, (const __half*)pWll,
            d_out, nullptr, bias, MTOK, OUTc, Dc);
    }
}